// round 10
// baseline (speedup 1.0000x reference)
#include <cuda_runtime.h>
#include <cuda_bf16.h>
#include <cuda_fp16.h>
#include <cstdint>

#define DD 128
#define MAXN 50016
#define MAXE 800000
#define SCAN_CHUNK 2048
#define MAXP ((MAXN + SCAN_CHUNK - 1) / SCAN_CHUNK)

// ---------------- scratch (device globals; allocation-free) ----------------
__device__ __align__(16) __nv_bfloat16 g_yhi[(size_t)MAXN * DD];  // post-agg hi
__device__ __align__(16) __nv_bfloat16 g_ylo[(size_t)MAXN * DD];  // post-agg lo
__device__ __align__(16) __half g_x16[(size_t)MAXN * DD];         // fp16 input copy
__device__ __align__(16) __half g_act16[(size_t)MAXN * DD];       // fp16 activations
__device__ __align__(16) __nv_bfloat16 g_whi[3 * DD * DD];
__device__ __align__(16) __nv_bfloat16 g_wlo[3 * DD * DD];
__device__ float g_dinv[MAXN];
__device__ __align__(16) int g_cnt[MAXN];
__device__ int   g_off[MAXN + 1];
__device__ int   g_cur[MAXN];
__device__ __align__(8) int2 g_em[MAXE];   // packed (src, ew bits)
__device__ int   g_partial[MAXP + 1];

// ---------------- helpers ----------------
__device__ __forceinline__ void split_bf16(float f, __nv_bfloat16& h, __nv_bfloat16& l) {
    h = __float2bfloat16(f);
    l = __float2bfloat16(f - __bfloat162float(h));
}
__device__ __forceinline__ void split2(float2 f, uint32_t& hu, uint32_t& lu) {
    __nv_bfloat16 h0, l0, h1, l1;
    split_bf16(f.x, h0, l0);
    split_bf16(f.y, h1, l1);
    union { __nv_bfloat162 b; uint32_t u; } c;
    c.b = __halves2bfloat162(h0, h1);
    hu = c.u;
    c.b = __halves2bfloat162(l0, l1);
    lu = c.u;
}

// ---------------------------------------------------------------------------
// init: zero cnt + transpose/split all 3 weight matrices (one launch)
// ---------------------------------------------------------------------------
__global__ __launch_bounds__(256) void init_kernel(int* __restrict__ cnt, int n, int nzb,
                                                   const float* __restrict__ W1,
                                                   const float* __restrict__ W2,
                                                   const float* __restrict__ W3,
                                                   __nv_bfloat16* __restrict__ whi,
                                                   __nv_bfloat16* __restrict__ wlo) {
    if ((int)blockIdx.x < nzb) {
        int i = blockIdx.x * 256 + threadIdx.x;
        if (i < n) cnt[i] = 0;
    } else {
        int i = (blockIdx.x - nzb) * 256 + threadIdx.x;
        if (i < 3 * DD * DD) {
            int layer = i / (DD * DD);
            int j = i - layer * (DD * DD);
            const float* W = (layer == 0) ? W1 : ((layer == 1) ? W2 : W3);
            int nn = j >> 7, kk = j & 127;
            float v = W[kk * DD + nn];
            __nv_bfloat16 h, l;
            split_bf16(v, h, l);
            whi[i] = h;
            wlo[i] = l;
        }
    }
}

// fp32 -> fp16 copy of x (4 floats per thread)
__global__ __launch_bounds__(256) void convert_x_kernel(const float* __restrict__ x,
                                                        __half* __restrict__ x16, int total4) {
    int i = blockIdx.x * blockDim.x + threadIdx.x;
    if (i >= total4) return;
    float4 v = ((const float4*)x)[i];
    __half2 a = __floats2half2_rn(v.x, v.y);
    __half2 b = __floats2half2_rn(v.z, v.w);
    uint2 u;
    u.x = *(uint32_t*)&a;
    u.y = *(uint32_t*)&b;
    ((uint2*)x16)[i] = u;
}

__global__ void count_kernel(const int* __restrict__ dst, int* __restrict__ cnt, int E) {
    int e = blockIdx.x * blockDim.x + threadIdx.x;
    if (e < E) atomicAdd(&cnt[dst[e]], 1);
}

// Phase 1: per-block sums. 1024 threads x 2 ints (int2 loads).
__global__ __launch_bounds__(1024) void scan_p1_kernel(const int* __restrict__ cnt,
                                                       int* __restrict__ partial, int n) {
    __shared__ int wsum[32];
    int t = threadIdx.x;
    int i0 = blockIdx.x * SCAN_CHUNK + t * 2;
    int s = 0;
    if (i0 + 1 < n) {
        int2 v = *(const int2*)(cnt + i0);
        s = v.x + v.y;
    } else if (i0 < n) {
        s = cnt[i0];
    }
#pragma unroll
    for (int o = 16; o > 0; o >>= 1) s += __shfl_down_sync(0xffffffffu, s, o);
    if ((t & 31) == 0) wsum[t >> 5] = s;
    __syncthreads();
    if (t < 32) {
        int v = wsum[t];
#pragma unroll
        for (int o = 16; o > 0; o >>= 1) v += __shfl_down_sync(0xffffffffu, v, o);
        if (t == 0) partial[blockIdx.x] = v;
    }
}

// Phase 3: merged top scan + per-block rescan. 1024 threads x 2 ints.
__global__ __launch_bounds__(1024) void scan_p3_kernel(const int* __restrict__ cnt,
                                                       const int* __restrict__ partial,
                                                       int* __restrict__ off,
                                                       int* __restrict__ cur,
                                                       float* __restrict__ dinv, int n, int np) {
    __shared__ int s_base;
    __shared__ int wsum[32];
    int t = threadIdx.x;
    int lane = t & 31;
    int warp = t >> 5;

    if (t < 32) {
        int v = (t < np) ? partial[t] : 0;
#pragma unroll
        for (int o = 1; o < 32; o <<= 1) {
            int u = __shfl_up_sync(0xffffffffu, v, o);
            if (t >= o) v += u;
        }
        int srcl = (int)blockIdx.x - 1;
        int excl = __shfl_sync(0xffffffffu, v, (srcl < 0) ? 0 : srcl);
        if (t == 0) s_base = (blockIdx.x == 0) ? 0 : excl;
        if (blockIdx.x == 0 && t == 31) off[n] = v;
    }

    int i0 = blockIdx.x * SCAN_CHUNK + t * 2;
    int c0 = 0, c1 = 0;
    if (i0 + 1 < n) {
        int2 v = *(const int2*)(cnt + i0);
        c0 = v.x;
        c1 = v.y;
    } else if (i0 < n) {
        c0 = cnt[i0];
    }
    int s = c0 + c1;
    int incl = s;
#pragma unroll
    for (int o = 1; o < 32; o <<= 1) {
        int u = __shfl_up_sync(0xffffffffu, incl, o);
        if (lane >= o) incl += u;
    }
    if (lane == 31) wsum[warp] = incl;
    __syncthreads();
    if (t < 32) {
        int v = wsum[t];
        int orig = v;
#pragma unroll
        for (int o = 1; o < 32; o <<= 1) {
            int u = __shfl_up_sync(0xffffffffu, v, o);
            if (t >= o) v += u;
        }
        wsum[t] = v - orig;
    }
    __syncthreads();
    int run = s_base + wsum[warp] + (incl - s);
    if (i0 < n) {
        off[i0] = run;
        cur[i0] = run;
        dinv[i0] = rsqrtf((float)(c0 + 1));
        run += c0;
        if (i0 + 1 < n) {
            off[i0 + 1] = run;
            cur[i0 + 1] = run;
            dinv[i0 + 1] = rsqrtf((float)(c1 + 1));
        }
    }
}

__global__ void fill_kernel(const int* __restrict__ src, const int* __restrict__ dst,
                            const float* __restrict__ dinv, int* __restrict__ cur,
                            int2* __restrict__ em, int E) {
    int e = blockIdx.x * blockDim.x + threadIdx.x;
    if (e >= E) return;
    int s = src[e];
    int d = dst[e];
    int pos = atomicAdd(&cur[d], 1);
    float w = dinv[s] * dinv[d];
    em[pos] = make_int2(s, __float_as_int(w));
}

// ---------------------------------------------------------------------------
// Aggregation: fp16 gather, fp32 accumulate, bf16 hi/lo split output.
// One warp per node; lane owns 4 features. Edge meta = packed int2.
// ---------------------------------------------------------------------------
__device__ __forceinline__ void fma_h4(float4& acc, float w, uint2 u) {
    __half2 a = *(__half2*)&u.x;
    __half2 b = *(__half2*)&u.y;
    float2 fa = __half22float2(a);
    float2 fb = __half22float2(b);
    acc.x = fmaf(w, fa.x, acc.x);
    acc.y = fmaf(w, fa.y, acc.y);
    acc.z = fmaf(w, fb.x, acc.z);
    acc.w = fmaf(w, fb.y, acc.w);
}

__global__ __launch_bounds__(256) void agg_kernel(const __half* __restrict__ h16,
                                                  const float* __restrict__ dinv,
                                                  const int* __restrict__ off,
                                                  const int2* __restrict__ em,
                                                  __nv_bfloat16* __restrict__ yhi,
                                                  __nv_bfloat16* __restrict__ ylo, int n) {
    int node = (blockIdx.x * blockDim.x + threadIdx.x) >> 5;
    int lane = threadIdx.x & 31;
    if (node >= n) return;

    const uint2* __restrict__ h2 = (const uint2*)h16;
    float di = dinv[node];
    float wself = di * di;
    float4 acc = make_float4(0.f, 0.f, 0.f, 0.f);
    fma_h4(acc, wself, h2[(size_t)node * 32 + lane]);

    int e = off[node], e1 = off[node + 1];
    for (; e + 3 < e1; e += 4) {
        int2 m0 = __ldg(&em[e]);
        int2 m1 = __ldg(&em[e + 1]);
        int2 m2 = __ldg(&em[e + 2]);
        int2 m3 = __ldg(&em[e + 3]);
        uint2 v0 = h2[(size_t)m0.x * 32 + lane];
        uint2 v1 = h2[(size_t)m1.x * 32 + lane];
        uint2 v2 = h2[(size_t)m2.x * 32 + lane];
        uint2 v3 = h2[(size_t)m3.x * 32 + lane];
        fma_h4(acc, __int_as_float(m0.y), v0);
        fma_h4(acc, __int_as_float(m1.y), v1);
        fma_h4(acc, __int_as_float(m2.y), v2);
        fma_h4(acc, __int_as_float(m3.y), v3);
    }
    for (; e < e1; ++e) {
        int2 m0 = __ldg(&em[e]);
        fma_h4(acc, __int_as_float(m0.y), h2[(size_t)m0.x * 32 + lane]);
    }

    // split epilogue: y -> bf16 hi/lo planes (removes split ALU from GEMM)
    uint32_t h0, l0, h1, l1;
    split2(make_float2(acc.x, acc.y), h0, l0);
    split2(make_float2(acc.z, acc.w), h1, l1);
    ((uint2*)yhi)[(size_t)node * 32 + lane] = make_uint2(h0, h1);
    ((uint2*)ylo)[(size_t)node * 32 + lane] = make_uint2(l0, l1);
}

// ---------------------------------------------------------------------------
// HMMA split-bf16 GEMM, A pre-split (hi/lo bf16 planes). Fused bias/ReLU.
// ---------------------------------------------------------------------------
#define BSTRIDE_U32 68

__device__ __forceinline__ void mma_bf16(float* c, const uint32_t* a, uint32_t b0, uint32_t b1) {
    asm volatile(
        "mma.sync.aligned.m16n8k16.row.col.f32.bf16.bf16.f32 "
        "{%0,%1,%2,%3}, {%4,%5,%6,%7}, {%8,%9}, {%0,%1,%2,%3};"
        : "+f"(c[0]), "+f"(c[1]), "+f"(c[2]), "+f"(c[3])
        : "r"(a[0]), "r"(a[1]), "r"(a[2]), "r"(a[3]), "r"(b0), "r"(b1));
}

template <int RELU, int F16OUT>
__global__ __launch_bounds__(256) void gemm_hmma_kernel(
    const __nv_bfloat16* __restrict__ Ahi, const __nv_bfloat16* __restrict__ Alo,
    const __nv_bfloat16* __restrict__ Whi, const __nv_bfloat16* __restrict__ Wlo,
    const float* __restrict__ bias, float* __restrict__ C32,
    __half* __restrict__ C16, int n) {
    extern __shared__ uint32_t sB[];
    uint32_t* sBh = sB;
    uint32_t* sBl = sB + 128 * BSTRIDE_U32;

    const int tid = threadIdx.x;
    const int warp = tid >> 5;
    const int lane = tid & 31;
    const int quad = lane >> 2;
    const int tq = lane & 3;
    const int row0 = blockIdx.x * 128;

    const uint32_t* Wh32 = (const uint32_t*)Whi;
    const uint32_t* Wl32 = (const uint32_t*)Wlo;
#pragma unroll
    for (int i = tid; i < 128 * 64; i += 256) {
        int r = i >> 6, kp = i & 63;
        sBh[r * BSTRIDE_U32 + kp] = Wh32[i];
        sBl[r * BSTRIDE_U32 + kp] = Wl32[i];
    }
    __syncthreads();

    const int row_lo = row0 + warp * 16 + quad;
    const int row_hi = row_lo + 8;
    const bool ok_lo = row_lo < n;
    const bool ok_hi = row_hi < n;

    float acc[16][4];
#pragma unroll
    for (int t = 0; t < 16; ++t)
#pragma unroll
        for (int j = 0; j < 4; ++j) acc[t][j] = 0.f;

#pragma unroll
    for (int ks = 0; ks < 8; ++ks) {
        const int k0 = ks * 16;
        uint32_t ah[4], al[4];
        {
            size_t base_lo = (size_t)row_lo * DD + k0 + 2 * tq;
            size_t base_hi = (size_t)row_hi * DD + k0 + 2 * tq;
            ah[0] = ok_lo ? *(const uint32_t*)(Ahi + base_lo) : 0u;
            ah[1] = ok_hi ? *(const uint32_t*)(Ahi + base_hi) : 0u;
            ah[2] = ok_lo ? *(const uint32_t*)(Ahi + base_lo + 8) : 0u;
            ah[3] = ok_hi ? *(const uint32_t*)(Ahi + base_hi + 8) : 0u;
            al[0] = ok_lo ? *(const uint32_t*)(Alo + base_lo) : 0u;
            al[1] = ok_hi ? *(const uint32_t*)(Alo + base_hi) : 0u;
            al[2] = ok_lo ? *(const uint32_t*)(Alo + base_lo + 8) : 0u;
            al[3] = ok_hi ? *(const uint32_t*)(Alo + base_hi + 8) : 0u;
        }
        const int kbase = (k0 >> 1) + tq;
#pragma unroll
        for (int nt = 0; nt < 16; ++nt) {
            int brow = nt * 8 + quad;
            uint32_t bh0 = sBh[brow * BSTRIDE_U32 + kbase];
            uint32_t bh1 = sBh[brow * BSTRIDE_U32 + kbase + 4];
            uint32_t bl0 = sBl[brow * BSTRIDE_U32 + kbase];
            uint32_t bl1 = sBl[brow * BSTRIDE_U32 + kbase + 4];
            mma_bf16(acc[nt], ah, bh0, bh1);
            mma_bf16(acc[nt], ah, bl0, bl1);
            mma_bf16(acc[nt], al, bh0, bh1);
        }
    }

#pragma unroll
    for (int nt = 0; nt < 16; ++nt) {
        int col = nt * 8 + 2 * tq;
        float2 bv = *(const float2*)(bias + col);
        float c0 = acc[nt][0] + bv.x, c1 = acc[nt][1] + bv.y;
        float c2 = acc[nt][2] + bv.x, c3 = acc[nt][3] + bv.y;
        if (RELU) {
            c0 = fmaxf(c0, 0.f); c1 = fmaxf(c1, 0.f);
            c2 = fmaxf(c2, 0.f); c3 = fmaxf(c3, 0.f);
        }
        if (F16OUT) {
            if (ok_lo) *(__half2*)(C16 + (size_t)row_lo * DD + col) = __floats2half2_rn(c0, c1);
            if (ok_hi) *(__half2*)(C16 + (size_t)row_hi * DD + col) = __floats2half2_rn(c2, c3);
        } else {
            if (ok_lo) *(float2*)(C32 + (size_t)row_lo * DD + col) = make_float2(c0, c1);
            if (ok_hi) *(float2*)(C32 + (size_t)row_hi * DD + col) = make_float2(c2, c3);
        }
    }
}

// ---------------------------------------------------------------------------
// Launch
// ---------------------------------------------------------------------------
extern "C" void kernel_launch(void* const* d_in, const int* in_sizes, int n_in,
                              void* d_out, int out_size) {
    const float* x  = (const float*)d_in[0];
    const int*   ei = (const int*)d_in[1];
    const float* W1 = (const float*)d_in[2];
    const float* b1 = (const float*)d_in[3];
    const float* W2 = (const float*)d_in[4];
    const float* b2 = (const float*)d_in[5];
    const float* W3 = (const float*)d_in[6];
    const float* b3 = (const float*)d_in[7];

    int n = in_sizes[0] / DD;
    int E = in_sizes[1] / 2;
    const int* src = ei;
    const int* dst = ei + E;

    float *dinv;
    __half *x16, *act16;
    __nv_bfloat16 *whi, *wlo, *yhi, *ylo;
    int *cnt, *off, *cur, *partial;
    int2* em;
    cudaGetSymbolAddress((void**)&yhi, g_yhi);
    cudaGetSymbolAddress((void**)&ylo, g_ylo);
    cudaGetSymbolAddress((void**)&x16, g_x16);
    cudaGetSymbolAddress((void**)&act16, g_act16);
    cudaGetSymbolAddress((void**)&whi, g_whi);
    cudaGetSymbolAddress((void**)&wlo, g_wlo);
    cudaGetSymbolAddress((void**)&dinv, g_dinv);
    cudaGetSymbolAddress((void**)&cnt, g_cnt);
    cudaGetSymbolAddress((void**)&off, g_off);
    cudaGetSymbolAddress((void**)&cur, g_cur);
    cudaGetSymbolAddress((void**)&em, g_em);
    cudaGetSymbolAddress((void**)&partial, g_partial);

    float* outp = (float*)d_out;

    const int GEMM_SMEM = 2 * 128 * BSTRIDE_U32 * 4;
    cudaFuncSetAttribute(gemm_hmma_kernel<1, 1>, cudaFuncAttributeMaxDynamicSharedMemorySize,
                         GEMM_SMEM);
    cudaFuncSetAttribute(gemm_hmma_kernel<0, 0>, cudaFuncAttributeMaxDynamicSharedMemorySize,
                         GEMM_SMEM);

    int tb = 256;
    int np = (n + SCAN_CHUNK - 1) / SCAN_CHUNK;
    int nzb = (n + 255) / 256;
    int wsb = (3 * DD * DD + 255) / 256;
    int tot4 = n * (DD / 4);

    // --- preprocess + weight prep + x16 ---
    init_kernel<<<nzb + wsb, 256>>>(cnt, n, nzb, W1, W2, W3, whi, wlo);
    convert_x_kernel<<<(tot4 + 255) / 256, 256>>>(x, x16, tot4);
    count_kernel<<<(E + tb - 1) / tb, tb>>>(dst, cnt, E);
    scan_p1_kernel<<<np, 1024>>>(cnt, partial, n);
    scan_p3_kernel<<<np, 1024>>>(cnt, partial, off, cur, dinv, n, np);
    fill_kernel<<<(E + tb - 1) / tb, tb>>>(src, dst, dinv, cur, em, E);

    int gemm_grid = (n + 127) / 128;
    int agg_grid = (n + 7) / 8;

    // Layer 1
    agg_kernel<<<agg_grid, 256>>>(x16, dinv, off, em, yhi, ylo, n);
    gemm_hmma_kernel<1, 1><<<gemm_grid, 256, GEMM_SMEM>>>(yhi, ylo, whi, wlo, b1, nullptr,
                                                          act16, n);
    // Layer 2
    agg_kernel<<<agg_grid, 256>>>(act16, dinv, off, em, yhi, ylo, n);
    gemm_hmma_kernel<1, 1><<<gemm_grid, 256, GEMM_SMEM>>>(yhi, ylo, whi + DD * DD,
                                                          wlo + DD * DD, b2, nullptr, act16, n);
    // Layer 3 (no relu) -> fp32 d_out
    agg_kernel<<<agg_grid, 256>>>(act16, dinv, off, em, yhi, ylo, n);
    gemm_hmma_kernel<0, 0><<<gemm_grid, 256, GEMM_SMEM>>>(yhi, ylo, whi + 2 * DD * DD,
                                                          wlo + 2 * DD * DD, b3, outp,
                                                          nullptr, n);
}

// round 11
// speedup vs baseline: 1.0798x; 1.0798x over previous
#include <cuda_runtime.h>
#include <cuda_bf16.h>
#include <cuda_fp16.h>
#include <cstdint>

#define DD 128
#define MAXN 50016
#define MAXE 800000
#define NB_SCAN 148   // scan/fill blocks (all co-resident => safe grid barrier)

// ---------------- scratch (device globals; allocation-free) ----------------
__device__ __align__(16) float g_y[(size_t)MAXN * DD];        // post-agg (fp32)
__device__ __align__(16) __half g_x16[(size_t)MAXN * DD];     // fp16 input copy
__device__ __align__(16) __half g_act16[(size_t)MAXN * DD];   // fp16 activations
__device__ __align__(16) __nv_bfloat16 g_whi[3 * DD * DD];
__device__ __align__(16) __nv_bfloat16 g_wlo[3 * DD * DD];
__device__ float g_dinv[MAXN];
__device__ __align__(16) int g_cnt[MAXN];   // static-zero; re-zeroed by scanfill each call
__device__ int   g_off[MAXN + 1];
__device__ int   g_cur[MAXN];
__device__ int   g_esrc[MAXE];
__device__ float g_ew[MAXE];
__device__ int   g_partial[256];
__device__ int   g_flag1;
__device__ int   g_flag2;

// ---------------- helpers ----------------
__device__ __forceinline__ void split_bf16(float f, __nv_bfloat16& h, __nv_bfloat16& l) {
    h = __float2bfloat16(f);
    l = __float2bfloat16(f - __bfloat162float(h));
}
__device__ __forceinline__ void split2(float2 f, uint32_t& hu, uint32_t& lu) {
    __nv_bfloat16 h0, l0, h1, l1;
    split_bf16(f.x, h0, l0);
    split_bf16(f.y, h1, l1);
    union { __nv_bfloat162 b; uint32_t u; } c;
    c.b = __halves2bfloat162(h0, h1);
    hu = c.u;
    c.b = __halves2bfloat162(l0, l1);
    lu = c.u;
}

// ---------------------------------------------------------------------------
// prep: count atomics (cnt pre-zeroed by previous call / static init) +
// weight transpose/split + x->fp16 convert + barrier-flag resets. One launch.
// ---------------------------------------------------------------------------
__global__ __launch_bounds__(256) void prep_kernel(
    const int* __restrict__ dst, int* __restrict__ cnt, int E, int ncb,
    const float* __restrict__ W1, const float* __restrict__ W2,
    const float* __restrict__ W3, __nv_bfloat16* __restrict__ whi,
    __nv_bfloat16* __restrict__ wlo, int wsb,
    const float* __restrict__ x, __half* __restrict__ x16, int tot4,
    int* __restrict__ flag1, int* __restrict__ flag2) {
    int b = (int)blockIdx.x;
    int t = threadIdx.x;
    if (b == 0 && t == 0) {
        *flag1 = 0;
        *flag2 = 0;
    }
    if (b < ncb) {
        int e = b * 256 + t;
        if (e < E) atomicAdd(&cnt[dst[e]], 1);
    } else if (b < ncb + wsb) {
        int i = (b - ncb) * 256 + t;
        if (i < 3 * DD * DD) {
            int layer = i / (DD * DD);
            int j = i - layer * (DD * DD);
            const float* W = (layer == 0) ? W1 : ((layer == 1) ? W2 : W3);
            int nn = j >> 7, kk = j & 127;
            float v = W[kk * DD + nn];
            __nv_bfloat16 h, l;
            split_bf16(v, h, l);
            whi[i] = h;
            wlo[i] = l;
        }
    } else {
        int i = (b - ncb - wsb) * 256 + t;
        if (i < tot4) {
            float4 v = ((const float4*)x)[i];
            __half2 a = __floats2half2_rn(v.x, v.y);
            __half2 c = __floats2half2_rn(v.z, v.w);
            uint2 u;
            u.x = *(uint32_t*)&a;
            u.y = *(uint32_t*)&c;
            ((uint2*)x16)[i] = u;
        }
    }
}

// ---------------------------------------------------------------------------
// scanfill: one kernel, NB_SCAN blocks x 1024 threads (all co-resident).
//   phase 1: local scan of cnt chunk -> partial[b], grid barrier
//   phase 2: top scan of partials -> off/cur/dinv, re-zero cnt, grid barrier
//   phase 3: grid-stride CSR fill (esrc, ew)
// ---------------------------------------------------------------------------
__global__ __launch_bounds__(1024) void scanfill_kernel(
    int* __restrict__ cnt, int* __restrict__ off, int* __restrict__ cur,
    float* __restrict__ dinv, const int* __restrict__ src,
    const int* __restrict__ dst, int* __restrict__ esrc, float* __restrict__ ew,
    int* __restrict__ partial, int* __restrict__ flag1, int* __restrict__ flag2,
    int n, int E, int ch) {
    __shared__ int wsum[32];
    __shared__ int sp[NB_SCAN];
    __shared__ int s_base;

    const int b = (int)blockIdx.x;
    const int t = threadIdx.x;
    const int lane = t & 31;
    const int w = t >> 5;
    const int nb = (int)gridDim.x;

    // ---- phase 1: local chunk scan ----
    int i = b * ch + t;
    int c = (t < ch && i < n) ? cnt[i] : 0;
    int incl = c;
#pragma unroll
    for (int o = 1; o < 32; o <<= 1) {
        int u = __shfl_up_sync(0xffffffffu, incl, o);
        if (lane >= o) incl += u;
    }
    if (lane == 31) wsum[w] = incl;
    __syncthreads();
    if (t < 32) {
        int v = wsum[t];
        int orig = v;
#pragma unroll
        for (int o = 1; o < 32; o <<= 1) {
            int u = __shfl_up_sync(0xffffffffu, v, o);
            if (t >= o) v += u;
        }
        int total = __shfl_sync(0xffffffffu, v, 31);
        wsum[t] = v - orig;  // exclusive warp prefix
        if (t == 0) {
            partial[b] = total;
            __threadfence();
            atomicAdd(flag1, 1);
            while (atomicAdd(flag1, 0) < nb) {}
            __threadfence();
        }
    }
    __syncthreads();

    // ---- phase 2: top scan of nb partials (Hillis-Steele in smem) ----
    if (t < nb) sp[t] = partial[t];
    __syncthreads();
    for (int o = 1; o < nb; o <<= 1) {
        int v = (t < nb && t >= o) ? sp[t - o] : 0;
        __syncthreads();
        if (t < nb) sp[t] += v;
        __syncthreads();
    }
    if (t == 0) s_base = (b == 0) ? 0 : sp[b - 1];
    __syncthreads();

    int run = s_base + wsum[w] + (incl - c);
    if (t < ch && i < n) {
        off[i] = run;
        cur[i] = run;
        dinv[i] = rsqrtf((float)(c + 1));
        cnt[i] = 0;  // restore for next kernel_launch call
    }
    if (b == 0 && t == 0) off[n] = sp[nb - 1];

    // ---- grid barrier 2 ----
    __threadfence();
    __syncthreads();
    if (t == 0) {
        atomicAdd(flag2, 1);
        while (atomicAdd(flag2, 0) < nb) {}
        __threadfence();
    }
    __syncthreads();

    // ---- phase 3: CSR fill (grid-stride) ----
    for (int e = b * 1024 + t; e < E; e += nb * 1024) {
        int s = src[e];
        int d = dst[e];
        int pos = atomicAdd(&cur[d], 1);
        esrc[pos] = s;
        ew[pos] = dinv[s] * dinv[d];
    }
}

// ---------------------------------------------------------------------------
// Aggregation (R9-exact): fp16 gather, fp32 accumulate, fp32 out.
// ---------------------------------------------------------------------------
__device__ __forceinline__ void fma_h4(float4& acc, float w, uint2 u) {
    __half2 a = *(__half2*)&u.x;
    __half2 b = *(__half2*)&u.y;
    float2 fa = __half22float2(a);
    float2 fb = __half22float2(b);
    acc.x = fmaf(w, fa.x, acc.x);
    acc.y = fmaf(w, fa.y, acc.y);
    acc.z = fmaf(w, fb.x, acc.z);
    acc.w = fmaf(w, fb.y, acc.w);
}

__global__ __launch_bounds__(256) void agg_kernel(const __half* __restrict__ h16,
                                                  const float* __restrict__ dinv,
                                                  const int* __restrict__ off,
                                                  const int* __restrict__ esrc,
                                                  const float* __restrict__ ew,
                                                  float* __restrict__ out, int n) {
    int node = (blockIdx.x * blockDim.x + threadIdx.x) >> 5;
    int lane = threadIdx.x & 31;
    if (node >= n) return;

    const uint2* __restrict__ h2 = (const uint2*)h16;
    float di = dinv[node];
    float wself = di * di;
    float4 acc = make_float4(0.f, 0.f, 0.f, 0.f);
    fma_h4(acc, wself, h2[(size_t)node * 32 + lane]);

    int e = off[node], e1 = off[node + 1];
    for (; e + 3 < e1; e += 4) {
        int s0 = __ldg(&esrc[e]);
        int s1 = __ldg(&esrc[e + 1]);
        int s2 = __ldg(&esrc[e + 2]);
        int s3 = __ldg(&esrc[e + 3]);
        float w0 = __ldg(&ew[e]);
        float w1 = __ldg(&ew[e + 1]);
        float w2 = __ldg(&ew[e + 2]);
        float w3 = __ldg(&ew[e + 3]);
        uint2 v0 = h2[(size_t)s0 * 32 + lane];
        uint2 v1 = h2[(size_t)s1 * 32 + lane];
        uint2 v2 = h2[(size_t)s2 * 32 + lane];
        uint2 v3 = h2[(size_t)s3 * 32 + lane];
        fma_h4(acc, w0, v0);
        fma_h4(acc, w1, v1);
        fma_h4(acc, w2, v2);
        fma_h4(acc, w3, v3);
    }
    for (; e < e1; ++e) {
        int s0 = __ldg(&esrc[e]);
        float w0 = __ldg(&ew[e]);
        fma_h4(acc, w0, h2[(size_t)s0 * 32 + lane]);
    }
    ((float4*)out)[(size_t)node * 32 + lane] = acc;
}

// ---------------------------------------------------------------------------
// HMMA split-bf16 GEMM (R9-exact): fp32 A, in-register split, bias/ReLU.
// ---------------------------------------------------------------------------
#define BSTRIDE_U32 68

__device__ __forceinline__ void mma_bf16(float* c, const uint32_t* a, uint32_t b0, uint32_t b1) {
    asm volatile(
        "mma.sync.aligned.m16n8k16.row.col.f32.bf16.bf16.f32 "
        "{%0,%1,%2,%3}, {%4,%5,%6,%7}, {%8,%9}, {%0,%1,%2,%3};"
        : "+f"(c[0]), "+f"(c[1]), "+f"(c[2]), "+f"(c[3])
        : "r"(a[0]), "r"(a[1]), "r"(a[2]), "r"(a[3]), "r"(b0), "r"(b1));
}

template <int RELU, int F16OUT>
__global__ __launch_bounds__(256) void gemm_hmma_kernel(
    const float* __restrict__ A,
    const __nv_bfloat16* __restrict__ Whi, const __nv_bfloat16* __restrict__ Wlo,
    const float* __restrict__ bias, float* __restrict__ C32,
    __half* __restrict__ C16, int n) {
    extern __shared__ uint32_t sB[];
    uint32_t* sBh = sB;
    uint32_t* sBl = sB + 128 * BSTRIDE_U32;

    const int tid = threadIdx.x;
    const int warp = tid >> 5;
    const int lane = tid & 31;
    const int quad = lane >> 2;
    const int tq = lane & 3;
    const int row0 = blockIdx.x * 128;

    const uint32_t* Wh32 = (const uint32_t*)Whi;
    const uint32_t* Wl32 = (const uint32_t*)Wlo;
#pragma unroll
    for (int i = tid; i < 128 * 64; i += 256) {
        int r = i >> 6, kp = i & 63;
        sBh[r * BSTRIDE_U32 + kp] = Wh32[i];
        sBl[r * BSTRIDE_U32 + kp] = Wl32[i];
    }
    __syncthreads();

    const int row_lo = row0 + warp * 16 + quad;
    const int row_hi = row_lo + 8;
    const bool ok_lo = row_lo < n;
    const bool ok_hi = row_hi < n;

    float acc[16][4];
#pragma unroll
    for (int t = 0; t < 16; ++t)
#pragma unroll
        for (int j = 0; j < 4; ++j) acc[t][j] = 0.f;

#pragma unroll
    for (int ks = 0; ks < 8; ++ks) {
        const int k0 = ks * 16;
        uint32_t ah[4], al[4];
        {
            const float2 z2 = make_float2(0.f, 0.f);
            size_t base_lo = (size_t)row_lo * DD + k0 + 2 * tq;
            size_t base_hi = (size_t)row_hi * DD + k0 + 2 * tq;
            float2 f0 = ok_lo ? *(const float2*)(A + base_lo) : z2;
            float2 f1 = ok_hi ? *(const float2*)(A + base_hi) : z2;
            float2 f2 = ok_lo ? *(const float2*)(A + base_lo + 8) : z2;
            float2 f3 = ok_hi ? *(const float2*)(A + base_hi + 8) : z2;
            split2(f0, ah[0], al[0]);
            split2(f1, ah[1], al[1]);
            split2(f2, ah[2], al[2]);
            split2(f3, ah[3], al[3]);
        }
        const int kbase = (k0 >> 1) + tq;
#pragma unroll
        for (int nt = 0; nt < 16; ++nt) {
            int brow = nt * 8 + quad;
            uint32_t bh0 = sBh[brow * BSTRIDE_U32 + kbase];
            uint32_t bh1 = sBh[brow * BSTRIDE_U32 + kbase + 4];
            uint32_t bl0 = sBl[brow * BSTRIDE_U32 + kbase];
            uint32_t bl1 = sBl[brow * BSTRIDE_U32 + kbase + 4];
            mma_bf16(acc[nt], ah, bh0, bh1);
            mma_bf16(acc[nt], ah, bl0, bl1);
            mma_bf16(acc[nt], al, bh0, bh1);
        }
    }

#pragma unroll
    for (int nt = 0; nt < 16; ++nt) {
        int col = nt * 8 + 2 * tq;
        float2 bv = *(const float2*)(bias + col);
        float c0 = acc[nt][0] + bv.x, c1 = acc[nt][1] + bv.y;
        float c2 = acc[nt][2] + bv.x, c3 = acc[nt][3] + bv.y;
        if (RELU) {
            c0 = fmaxf(c0, 0.f); c1 = fmaxf(c1, 0.f);
            c2 = fmaxf(c2, 0.f); c3 = fmaxf(c3, 0.f);
        }
        if (F16OUT) {
            if (ok_lo) *(__half2*)(C16 + (size_t)row_lo * DD + col) = __floats2half2_rn(c0, c1);
            if (ok_hi) *(__half2*)(C16 + (size_t)row_hi * DD + col) = __floats2half2_rn(c2, c3);
        } else {
            if (ok_lo) *(float2*)(C32 + (size_t)row_lo * DD + col) = make_float2(c0, c1);
            if (ok_hi) *(float2*)(C32 + (size_t)row_hi * DD + col) = make_float2(c2, c3);
        }
    }
}

// ---------------------------------------------------------------------------
// Launch: 8 kernels total (prep, scanfill, 3x[agg, gemm])
// ---------------------------------------------------------------------------
extern "C" void kernel_launch(void* const* d_in, const int* in_sizes, int n_in,
                              void* d_out, int out_size) {
    const float* x  = (const float*)d_in[0];
    const int*   ei = (const int*)d_in[1];
    const float* W1 = (const float*)d_in[2];
    const float* b1 = (const float*)d_in[3];
    const float* W2 = (const float*)d_in[4];
    const float* b2 = (const float*)d_in[5];
    const float* W3 = (const float*)d_in[6];
    const float* b3 = (const float*)d_in[7];

    int n = in_sizes[0] / DD;
    int E = in_sizes[1] / 2;
    const int* src = ei;
    const int* dst = ei + E;

    float *y, *dinv, *ew;
    __half *x16, *act16;
    __nv_bfloat16 *whi, *wlo;
    int *cnt, *off, *cur, *esrc, *partial, *flag1, *flag2;
    cudaGetSymbolAddress((void**)&y, g_y);
    cudaGetSymbolAddress((void**)&x16, g_x16);
    cudaGetSymbolAddress((void**)&act16, g_act16);
    cudaGetSymbolAddress((void**)&whi, g_whi);
    cudaGetSymbolAddress((void**)&wlo, g_wlo);
    cudaGetSymbolAddress((void**)&dinv, g_dinv);
    cudaGetSymbolAddress((void**)&cnt, g_cnt);
    cudaGetSymbolAddress((void**)&off, g_off);
    cudaGetSymbolAddress((void**)&cur, g_cur);
    cudaGetSymbolAddress((void**)&esrc, g_esrc);
    cudaGetSymbolAddress((void**)&ew, g_ew);
    cudaGetSymbolAddress((void**)&partial, g_partial);
    cudaGetSymbolAddress((void**)&flag1, g_flag1);
    cudaGetSymbolAddress((void**)&flag2, g_flag2);

    float* outp = (float*)d_out;

    const int GEMM_SMEM = 2 * 128 * BSTRIDE_U32 * 4;
    cudaFuncSetAttribute(gemm_hmma_kernel<1, 1>, cudaFuncAttributeMaxDynamicSharedMemorySize,
                         GEMM_SMEM);
    cudaFuncSetAttribute(gemm_hmma_kernel<0, 0>, cudaFuncAttributeMaxDynamicSharedMemorySize,
                         GEMM_SMEM);

    int tot4 = n * (DD / 4);
    int ncb = (E + 255) / 256;
    int wsb = (3 * DD * DD + 255) / 256;
    int cvb = (tot4 + 255) / 256;
    int ch = (n + NB_SCAN - 1) / NB_SCAN;  // elems per scan block (<=1024)

    // --- preprocess: 2 launches ---
    prep_kernel<<<ncb + wsb + cvb, 256>>>(dst, cnt, E, ncb, W1, W2, W3, whi, wlo, wsb, x, x16,
                                          tot4, flag1, flag2);
    scanfill_kernel<<<NB_SCAN, 1024>>>(cnt, off, cur, dinv, src, dst, esrc, ew, partial,
                                       flag1, flag2, n, E, ch);

    int gemm_grid = (n + 127) / 128;
    int agg_grid = (n + 7) / 8;

    // Layer 1
    agg_kernel<<<agg_grid, 256>>>(x16, dinv, off, esrc, ew, y, n);
    gemm_hmma_kernel<1, 1><<<gemm_grid, 256, GEMM_SMEM>>>(y, whi, wlo, b1, nullptr, act16, n);
    // Layer 2
    agg_kernel<<<agg_grid, 256>>>(act16, dinv, off, esrc, ew, y, n);
    gemm_hmma_kernel<1, 1><<<gemm_grid, 256, GEMM_SMEM>>>(y, whi + DD * DD, wlo + DD * DD, b2,
                                                          nullptr, act16, n);
    // Layer 3 (no relu) -> fp32 d_out
    agg_kernel<<<agg_grid, 256>>>(act16, dinv, off, esrc, ew, y, n);
    gemm_hmma_kernel<0, 0><<<gemm_grid, 256, GEMM_SMEM>>>(y, whi + 2 * DD * DD,
                                                          wlo + 2 * DD * DD, b3, outp,
                                                          nullptr, n);
}

// round 12
// speedup vs baseline: 1.0841x; 1.0040x over previous
#include <cuda_runtime.h>
#include <cuda_bf16.h>
#include <cuda_fp16.h>
#include <cstdint>

#define DD 128
#define MAXN 50016
#define MAXE 800000
#define NB_SCAN 148   // scan/fill blocks (all co-resident => safe grid barrier)

// ---------------- scratch (device globals; allocation-free) ----------------
__device__ __align__(16) float g_y[(size_t)MAXN * DD];        // post-agg (fp32)
__device__ __align__(16) __half g_x16[(size_t)MAXN * DD];     // fp16 input copy
__device__ __align__(16) __half g_act16[(size_t)MAXN * DD];   // fp16 activations
__device__ __align__(16) __nv_bfloat16 g_whi[3 * DD * DD];
__device__ __align__(16) __nv_bfloat16 g_wlo[3 * DD * DD];
__device__ float g_dinv[MAXN];
__device__ __align__(16) int g_cnt[MAXN];   // static-zero; re-zeroed by scanfill each call
__device__ int   g_off[MAXN + 1];
__device__ int   g_cur[MAXN];
__device__ int   g_esrc[MAXE];
__device__ float g_ew[MAXE];
__device__ int   g_partial[256];
__device__ int   g_flag1;
__device__ int   g_flag2;

// ---------------- helpers ----------------
__device__ __forceinline__ void split_bf16(float f, __nv_bfloat16& h, __nv_bfloat16& l) {
    h = __float2bfloat16(f);
    l = __float2bfloat16(f - __bfloat162float(h));
}
__device__ __forceinline__ void split2(float2 f, uint32_t& hu, uint32_t& lu) {
    __nv_bfloat16 h0, l0, h1, l1;
    split_bf16(f.x, h0, l0);
    split_bf16(f.y, h1, l1);
    union { __nv_bfloat162 b; uint32_t u; } c;
    c.b = __halves2bfloat162(h0, h1);
    hu = c.u;
    c.b = __halves2bfloat162(l0, l1);
    lu = c.u;
}

// ---------------------------------------------------------------------------
// prep: count atomics (cnt pre-zeroed by previous call / static init) +
// weight transpose/split + x->fp16 convert + barrier-flag resets. One launch.
// ---------------------------------------------------------------------------
__global__ __launch_bounds__(256) void prep_kernel(
    const int* __restrict__ dst, int* __restrict__ cnt, int E, int ncb,
    const float* __restrict__ W1, const float* __restrict__ W2,
    const float* __restrict__ W3, __nv_bfloat16* __restrict__ whi,
    __nv_bfloat16* __restrict__ wlo, int wsb,
    const float* __restrict__ x, __half* __restrict__ x16, int tot4,
    int* __restrict__ flag1, int* __restrict__ flag2) {
    int b = (int)blockIdx.x;
    int t = threadIdx.x;
    if (b == 0 && t == 0) {
        *flag1 = 0;
        *flag2 = 0;
    }
    if (b < ncb) {
        int e = b * 256 + t;
        if (e < E) atomicAdd(&cnt[dst[e]], 1);
    } else if (b < ncb + wsb) {
        int i = (b - ncb) * 256 + t;
        if (i < 3 * DD * DD) {
            int layer = i / (DD * DD);
            int j = i - layer * (DD * DD);
            const float* W = (layer == 0) ? W1 : ((layer == 1) ? W2 : W3);
            int nn = j >> 7, kk = j & 127;
            float v = W[kk * DD + nn];
            __nv_bfloat16 h, l;
            split_bf16(v, h, l);
            whi[i] = h;
            wlo[i] = l;
        }
    } else {
        int i = (b - ncb - wsb) * 256 + t;
        if (i < tot4) {
            float4 v = ((const float4*)x)[i];
            __half2 a = __floats2half2_rn(v.x, v.y);
            __half2 c = __floats2half2_rn(v.z, v.w);
            uint2 u;
            u.x = *(uint32_t*)&a;
            u.y = *(uint32_t*)&c;
            ((uint2*)x16)[i] = u;
        }
    }
}

// ---------------------------------------------------------------------------
// scanfill: one kernel, NB_SCAN blocks x 1024 threads (all co-resident).
//   phase 1: local scan of cnt chunk -> partial[b], grid barrier
//   phase 2: top scan of partials -> off/cur/dinv, re-zero cnt, grid barrier
//   phase 3: grid-stride CSR fill (esrc, ew)
// ---------------------------------------------------------------------------
__global__ __launch_bounds__(1024) void scanfill_kernel(
    int* __restrict__ cnt, int* __restrict__ off, int* __restrict__ cur,
    float* __restrict__ dinv, const int* __restrict__ src,
    const int* __restrict__ dst, int* __restrict__ esrc, float* __restrict__ ew,
    int* __restrict__ partial, int* __restrict__ flag1, int* __restrict__ flag2,
    int n, int E, int ch) {
    __shared__ int wsum[32];
    __shared__ int sp[NB_SCAN];
    __shared__ int s_base;

    const int b = (int)blockIdx.x;
    const int t = threadIdx.x;
    const int lane = t & 31;
    const int w = t >> 5;
    const int nb = (int)gridDim.x;

    // ---- phase 1: local chunk scan ----
    int i = b * ch + t;
    int c = (t < ch && i < n) ? cnt[i] : 0;
    int incl = c;
#pragma unroll
    for (int o = 1; o < 32; o <<= 1) {
        int u = __shfl_up_sync(0xffffffffu, incl, o);
        if (lane >= o) incl += u;
    }
    if (lane == 31) wsum[w] = incl;
    __syncthreads();
    if (t < 32) {
        int v = wsum[t];
        int orig = v;
#pragma unroll
        for (int o = 1; o < 32; o <<= 1) {
            int u = __shfl_up_sync(0xffffffffu, v, o);
            if (t >= o) v += u;
        }
        int total = __shfl_sync(0xffffffffu, v, 31);
        wsum[t] = v - orig;  // exclusive warp prefix
        if (t == 0) {
            partial[b] = total;
            __threadfence();
            atomicAdd(flag1, 1);
            while (atomicAdd(flag1, 0) < nb) {}
            __threadfence();
        }
    }
    __syncthreads();

    // ---- phase 2: top scan of nb partials (Hillis-Steele in smem) ----
    if (t < nb) sp[t] = partial[t];
    __syncthreads();
    for (int o = 1; o < nb; o <<= 1) {
        int v = (t < nb && t >= o) ? sp[t - o] : 0;
        __syncthreads();
        if (t < nb) sp[t] += v;
        __syncthreads();
    }
    if (t == 0) s_base = (b == 0) ? 0 : sp[b - 1];
    __syncthreads();

    int run = s_base + wsum[w] + (incl - c);
    if (t < ch && i < n) {
        off[i] = run;
        cur[i] = run;
        dinv[i] = rsqrtf((float)(c + 1));
        cnt[i] = 0;  // restore for next kernel_launch call
    }
    if (b == 0 && t == 0) off[n] = sp[nb - 1];

    // ---- grid barrier 2 ----
    __threadfence();
    __syncthreads();
    if (t == 0) {
        atomicAdd(flag2, 1);
        while (atomicAdd(flag2, 0) < nb) {}
        __threadfence();
    }
    __syncthreads();

    // ---- phase 3: CSR fill (grid-stride) ----
    for (int e = b * 1024 + t; e < E; e += nb * 1024) {
        int s = src[e];
        int d = dst[e];
        int pos = atomicAdd(&cur[d], 1);
        esrc[pos] = s;
        ew[pos] = dinv[s] * dinv[d];
    }
}

// ---------------------------------------------------------------------------
// Aggregation (R9-exact): fp16 gather, fp32 accumulate, fp32 out.
// ---------------------------------------------------------------------------
__device__ __forceinline__ void fma_h4(float4& acc, float w, uint2 u) {
    __half2 a = *(__half2*)&u.x;
    __half2 b = *(__half2*)&u.y;
    float2 fa = __half22float2(a);
    float2 fb = __half22float2(b);
    acc.x = fmaf(w, fa.x, acc.x);
    acc.y = fmaf(w, fa.y, acc.y);
    acc.z = fmaf(w, fb.x, acc.z);
    acc.w = fmaf(w, fb.y, acc.w);
}

__global__ __launch_bounds__(256) void agg_kernel(const __half* __restrict__ h16,
                                                  const float* __restrict__ dinv,
                                                  const int* __restrict__ off,
                                                  const int* __restrict__ esrc,
                                                  const float* __restrict__ ew,
                                                  float* __restrict__ out, int n) {
    int node = (blockIdx.x * blockDim.x + threadIdx.x) >> 5;
    int lane = threadIdx.x & 31;
    if (node >= n) return;

    const uint2* __restrict__ h2 = (const uint2*)h16;
    float di = dinv[node];
    float wself = di * di;
    float4 acc = make_float4(0.f, 0.f, 0.f, 0.f);
    fma_h4(acc, wself, h2[(size_t)node * 32 + lane]);

    int e = off[node], e1 = off[node + 1];
    for (; e + 3 < e1; e += 4) {
        int s0 = __ldg(&esrc[e]);
        int s1 = __ldg(&esrc[e + 1]);
        int s2 = __ldg(&esrc[e + 2]);
        int s3 = __ldg(&esrc[e + 3]);
        float w0 = __ldg(&ew[e]);
        float w1 = __ldg(&ew[e + 1]);
        float w2 = __ldg(&ew[e + 2]);
        float w3 = __ldg(&ew[e + 3]);
        uint2 v0 = h2[(size_t)s0 * 32 + lane];
        uint2 v1 = h2[(size_t)s1 * 32 + lane];
        uint2 v2 = h2[(size_t)s2 * 32 + lane];
        uint2 v3 = h2[(size_t)s3 * 32 + lane];
        fma_h4(acc, w0, v0);
        fma_h4(acc, w1, v1);
        fma_h4(acc, w2, v2);
        fma_h4(acc, w3, v3);
    }
    for (; e < e1; ++e) {
        int s0 = __ldg(&esrc[e]);
        float w0 = __ldg(&ew[e]);
        fma_h4(acc, w0, h2[(size_t)s0 * 32 + lane]);
    }
    ((float4*)out)[(size_t)node * 32 + lane] = acc;
}

// ---------------------------------------------------------------------------
// HMMA split-bf16 GEMM (R9-exact): fp32 A, in-register split, bias/ReLU.
// ---------------------------------------------------------------------------
#define BSTRIDE_U32 68

__device__ __forceinline__ void mma_bf16(float* c, const uint32_t* a, uint32_t b0, uint32_t b1) {
    asm volatile(
        "mma.sync.aligned.m16n8k16.row.col.f32.bf16.bf16.f32 "
        "{%0,%1,%2,%3}, {%4,%5,%6,%7}, {%8,%9}, {%0,%1,%2,%3};"
        : "+f"(c[0]), "+f"(c[1]), "+f"(c[2]), "+f"(c[3])
        : "r"(a[0]), "r"(a[1]), "r"(a[2]), "r"(a[3]), "r"(b0), "r"(b1));
}

template <int RELU, int F16OUT>
__global__ __launch_bounds__(256) void gemm_hmma_kernel(
    const float* __restrict__ A,
    const __nv_bfloat16* __restrict__ Whi, const __nv_bfloat16* __restrict__ Wlo,
    const float* __restrict__ bias, float* __restrict__ C32,
    __half* __restrict__ C16, int n) {
    extern __shared__ uint32_t sB[];
    uint32_t* sBh = sB;
    uint32_t* sBl = sB + 128 * BSTRIDE_U32;

    const int tid = threadIdx.x;
    const int warp = tid >> 5;
    const int lane = tid & 31;
    const int quad = lane >> 2;
    const int tq = lane & 3;
    const int row0 = blockIdx.x * 128;

    const uint32_t* Wh32 = (const uint32_t*)Whi;
    const uint32_t* Wl32 = (const uint32_t*)Wlo;
#pragma unroll
    for (int i = tid; i < 128 * 64; i += 256) {
        int r = i >> 6, kp = i & 63;
        sBh[r * BSTRIDE_U32 + kp] = Wh32[i];
        sBl[r * BSTRIDE_U32 + kp] = Wl32[i];
    }
    __syncthreads();

    const int row_lo = row0 + warp * 16 + quad;
    const int row_hi = row_lo + 8;
    const bool ok_lo = row_lo < n;
    const bool ok_hi = row_hi < n;

    float acc[16][4];
#pragma unroll
    for (int t = 0; t < 16; ++t)
#pragma unroll
        for (int j = 0; j < 4; ++j) acc[t][j] = 0.f;

#pragma unroll
    for (int ks = 0; ks < 8; ++ks) {
        const int k0 = ks * 16;
        uint32_t ah[4], al[4];
        {
            const float2 z2 = make_float2(0.f, 0.f);
            size_t base_lo = (size_t)row_lo * DD + k0 + 2 * tq;
            size_t base_hi = (size_t)row_hi * DD + k0 + 2 * tq;
            float2 f0 = ok_lo ? *(const float2*)(A + base_lo) : z2;
            float2 f1 = ok_hi ? *(const float2*)(A + base_hi) : z2;
            float2 f2 = ok_lo ? *(const float2*)(A + base_lo + 8) : z2;
            float2 f3 = ok_hi ? *(const float2*)(A + base_hi + 8) : z2;
            split2(f0, ah[0], al[0]);
            split2(f1, ah[1], al[1]);
            split2(f2, ah[2], al[2]);
            split2(f3, ah[3], al[3]);
        }
        const int kbase = (k0 >> 1) + tq;
#pragma unroll
        for (int nt = 0; nt < 16; ++nt) {
            int brow = nt * 8 + quad;
            uint32_t bh0 = sBh[brow * BSTRIDE_U32 + kbase];
            uint32_t bh1 = sBh[brow * BSTRIDE_U32 + kbase + 4];
            uint32_t bl0 = sBl[brow * BSTRIDE_U32 + kbase];
            uint32_t bl1 = sBl[brow * BSTRIDE_U32 + kbase + 4];
            mma_bf16(acc[nt], ah, bh0, bh1);
            mma_bf16(acc[nt], ah, bl0, bl1);
            mma_bf16(acc[nt], al, bh0, bh1);
        }
    }

#pragma unroll
    for (int nt = 0; nt < 16; ++nt) {
        int col = nt * 8 + 2 * tq;
        float2 bv = *(const float2*)(bias + col);
        float c0 = acc[nt][0] + bv.x, c1 = acc[nt][1] + bv.y;
        float c2 = acc[nt][2] + bv.x, c3 = acc[nt][3] + bv.y;
        if (RELU) {
            c0 = fmaxf(c0, 0.f); c1 = fmaxf(c1, 0.f);
            c2 = fmaxf(c2, 0.f); c3 = fmaxf(c3, 0.f);
        }
        if (F16OUT) {
            if (ok_lo) *(__half2*)(C16 + (size_t)row_lo * DD + col) = __floats2half2_rn(c0, c1);
            if (ok_hi) *(__half2*)(C16 + (size_t)row_hi * DD + col) = __floats2half2_rn(c2, c3);
        } else {
            if (ok_lo) *(float2*)(C32 + (size_t)row_lo * DD + col) = make_float2(c0, c1);
            if (ok_hi) *(float2*)(C32 + (size_t)row_hi * DD + col) = make_float2(c2, c3);
        }
    }
}

// ---------------------------------------------------------------------------
// Launch: 8 kernels total (prep, scanfill, 3x[agg, gemm])
// ---------------------------------------------------------------------------
extern "C" void kernel_launch(void* const* d_in, const int* in_sizes, int n_in,
                              void* d_out, int out_size) {
    const float* x  = (const float*)d_in[0];
    const int*   ei = (const int*)d_in[1];
    const float* W1 = (const float*)d_in[2];
    const float* b1 = (const float*)d_in[3];
    const float* W2 = (const float*)d_in[4];
    const float* b2 = (const float*)d_in[5];
    const float* W3 = (const float*)d_in[6];
    const float* b3 = (const float*)d_in[7];

    int n = in_sizes[0] / DD;
    int E = in_sizes[1] / 2;
    const int* src = ei;
    const int* dst = ei + E;

    float *y, *dinv, *ew;
    __half *x16, *act16;
    __nv_bfloat16 *whi, *wlo;
    int *cnt, *off, *cur, *esrc, *partial, *flag1, *flag2;
    cudaGetSymbolAddress((void**)&y, g_y);
    cudaGetSymbolAddress((void**)&x16, g_x16);
    cudaGetSymbolAddress((void**)&act16, g_act16);
    cudaGetSymbolAddress((void**)&whi, g_whi);
    cudaGetSymbolAddress((void**)&wlo, g_wlo);
    cudaGetSymbolAddress((void**)&dinv, g_dinv);
    cudaGetSymbolAddress((void**)&cnt, g_cnt);
    cudaGetSymbolAddress((void**)&off, g_off);
    cudaGetSymbolAddress((void**)&cur, g_cur);
    cudaGetSymbolAddress((void**)&esrc, g_esrc);
    cudaGetSymbolAddress((void**)&ew, g_ew);
    cudaGetSymbolAddress((void**)&partial, g_partial);
    cudaGetSymbolAddress((void**)&flag1, g_flag1);
    cudaGetSymbolAddress((void**)&flag2, g_flag2);

    float* outp = (float*)d_out;

    const int GEMM_SMEM = 2 * 128 * BSTRIDE_U32 * 4;
    cudaFuncSetAttribute(gemm_hmma_kernel<1, 1>, cudaFuncAttributeMaxDynamicSharedMemorySize,
                         GEMM_SMEM);
    cudaFuncSetAttribute(gemm_hmma_kernel<0, 0>, cudaFuncAttributeMaxDynamicSharedMemorySize,
                         GEMM_SMEM);

    int tot4 = n * (DD / 4);
    int ncb = (E + 255) / 256;
    int wsb = (3 * DD * DD + 255) / 256;
    int cvb = (tot4 + 255) / 256;
    int ch = (n + NB_SCAN - 1) / NB_SCAN;  // elems per scan block (<=1024)

    // --- preprocess: 2 launches ---
    prep_kernel<<<ncb + wsb + cvb, 256>>>(dst, cnt, E, ncb, W1, W2, W3, whi, wlo, wsb, x, x16,
                                          tot4, flag1, flag2);
    scanfill_kernel<<<NB_SCAN, 1024>>>(cnt, off, cur, dinv, src, dst, esrc, ew, partial,
                                       flag1, flag2, n, E, ch);

    int gemm_grid = (n + 127) / 128;
    int agg_grid = (n + 7) / 8;

    // Layer 1
    agg_kernel<<<agg_grid, 256>>>(x16, dinv, off, esrc, ew, y, n);
    gemm_hmma_kernel<1, 1><<<gemm_grid, 256, GEMM_SMEM>>>(y, whi, wlo, b1, nullptr, act16, n);
    // Layer 2
    agg_kernel<<<agg_grid, 256>>>(act16, dinv, off, esrc, ew, y, n);
    gemm_hmma_kernel<1, 1><<<gemm_grid, 256, GEMM_SMEM>>>(y, whi + DD * DD, wlo + DD * DD, b2,
                                                          nullptr, act16, n);
    // Layer 3 (no relu) -> fp32 d_out
    agg_kernel<<<agg_grid, 256>>>(act16, dinv, off, esrc, ew, y, n);
    gemm_hmma_kernel<0, 0><<<gemm_grid, 256, GEMM_SMEM>>>(y, whi + 2 * DD * DD,
                                                          wlo + 2 * DD * DD, b3, outp,
                                                          nullptr, n);
}

// round 13
// speedup vs baseline: 1.2328x; 1.1371x over previous
#include <cuda_runtime.h>
#include <cuda_bf16.h>
#include <cuda_fp16.h>
#include <cstdint>

#define DD 128
#define MAXN 50016
#define MAXE 800000
#define NB_SCAN 148   // scan/fill blocks (all co-resident => safe grid barrier)

// ---------------- scratch (device globals; allocation-free) ----------------
__device__ __align__(16) __half g_y16[(size_t)MAXN * DD];     // post-agg (fp16)
__device__ __align__(16) __half g_x16[(size_t)MAXN * DD];     // fp16 input copy
__device__ __align__(16) __half g_act16[(size_t)MAXN * DD];   // fp16 activations
__device__ __align__(16) __half g_w16[3 * DD * DD];           // W^T fp16 per layer
__device__ float g_dinv[MAXN];
__device__ __align__(16) int g_cnt[MAXN];   // static-zero; re-zeroed by scanfill each call
__device__ int   g_off[MAXN + 1];
__device__ int   g_cur[MAXN];
__device__ int   g_esrc[MAXE];
__device__ float g_ew[MAXE];
__device__ int   g_partial[256];
__device__ int   g_flag1;
__device__ int   g_flag2;

// ---------------------------------------------------------------------------
// prep: count atomics + W transpose->fp16 + x->fp16 + flag resets. One launch.
// ---------------------------------------------------------------------------
__global__ __launch_bounds__(256) void prep_kernel(
    const int* __restrict__ dst, int* __restrict__ cnt, int E, int ncb,
    const float* __restrict__ W1, const float* __restrict__ W2,
    const float* __restrict__ W3, __half* __restrict__ w16, int wsb,
    const float* __restrict__ x, __half* __restrict__ x16, int tot4,
    int* __restrict__ flag1, int* __restrict__ flag2) {
    int b = (int)blockIdx.x;
    int t = threadIdx.x;
    if (b == 0 && t == 0) {
        *flag1 = 0;
        *flag2 = 0;
    }
    if (b < ncb) {
        int e = b * 256 + t;
        if (e < E) atomicAdd(&cnt[dst[e]], 1);
    } else if (b < ncb + wsb) {
        int i = (b - ncb) * 256 + t;
        if (i < 3 * DD * DD) {
            int layer = i / (DD * DD);
            int j = i - layer * (DD * DD);
            const float* W = (layer == 0) ? W1 : ((layer == 1) ? W2 : W3);
            int nn = j >> 7, kk = j & 127;
            w16[i] = __float2half(W[kk * DD + nn]);
        }
    } else {
        int i = (b - ncb - wsb) * 256 + t;
        if (i < tot4) {
            float4 v = ((const float4*)x)[i];
            __half2 a = __floats2half2_rn(v.x, v.y);
            __half2 c = __floats2half2_rn(v.z, v.w);
            uint2 u;
            u.x = *(uint32_t*)&a;
            u.y = *(uint32_t*)&c;
            ((uint2*)x16)[i] = u;
        }
    }
}

// ---------------------------------------------------------------------------
// scanfill: one kernel, NB_SCAN blocks x 1024 threads (all co-resident).
// ---------------------------------------------------------------------------
__global__ __launch_bounds__(1024) void scanfill_kernel(
    int* __restrict__ cnt, int* __restrict__ off, int* __restrict__ cur,
    float* __restrict__ dinv, const int* __restrict__ src,
    const int* __restrict__ dst, int* __restrict__ esrc, float* __restrict__ ew,
    int* __restrict__ partial, int* __restrict__ flag1, int* __restrict__ flag2,
    int n, int E, int ch) {
    __shared__ int wsum[32];
    __shared__ int sp[NB_SCAN];
    __shared__ int s_base;

    const int b = (int)blockIdx.x;
    const int t = threadIdx.x;
    const int lane = t & 31;
    const int w = t >> 5;
    const int nb = (int)gridDim.x;

    // ---- phase 1: local chunk scan ----
    int i = b * ch + t;
    int c = (t < ch && i < n) ? cnt[i] : 0;
    int incl = c;
#pragma unroll
    for (int o = 1; o < 32; o <<= 1) {
        int u = __shfl_up_sync(0xffffffffu, incl, o);
        if (lane >= o) incl += u;
    }
    if (lane == 31) wsum[w] = incl;
    __syncthreads();
    if (t < 32) {
        int v = wsum[t];
        int orig = v;
#pragma unroll
        for (int o = 1; o < 32; o <<= 1) {
            int u = __shfl_up_sync(0xffffffffu, v, o);
            if (t >= o) v += u;
        }
        int total = __shfl_sync(0xffffffffu, v, 31);
        wsum[t] = v - orig;
        if (t == 0) {
            partial[b] = total;
            __threadfence();
            atomicAdd(flag1, 1);
            while (atomicAdd(flag1, 0) < nb) {}
            __threadfence();
        }
    }
    __syncthreads();

    // ---- phase 2: top scan of nb partials ----
    if (t < nb) sp[t] = partial[t];
    __syncthreads();
    for (int o = 1; o < nb; o <<= 1) {
        int v = (t < nb && t >= o) ? sp[t - o] : 0;
        __syncthreads();
        if (t < nb) sp[t] += v;
        __syncthreads();
    }
    if (t == 0) s_base = (b == 0) ? 0 : sp[b - 1];
    __syncthreads();

    int run = s_base + wsum[w] + (incl - c);
    if (t < ch && i < n) {
        off[i] = run;
        cur[i] = run;
        dinv[i] = rsqrtf((float)(c + 1));
        cnt[i] = 0;
    }
    if (b == 0 && t == 0) off[n] = sp[nb - 1];

    // ---- grid barrier 2 ----
    __threadfence();
    __syncthreads();
    if (t == 0) {
        atomicAdd(flag2, 1);
        while (atomicAdd(flag2, 0) < nb) {}
        __threadfence();
    }
    __syncthreads();

    // ---- phase 3: CSR fill (grid-stride) ----
    for (int e = b * 1024 + t; e < E; e += nb * 1024) {
        int s = src[e];
        int d = dst[e];
        int pos = atomicAdd(&cur[d], 1);
        esrc[pos] = s;
        ew[pos] = dinv[s] * dinv[d];
    }
}

// ---------------------------------------------------------------------------
// Aggregation: fp16 gather, fp32 accumulate, fp16 out.
// ---------------------------------------------------------------------------
__device__ __forceinline__ void fma_h4(float4& acc, float w, uint2 u) {
    __half2 a = *(__half2*)&u.x;
    __half2 b = *(__half2*)&u.y;
    float2 fa = __half22float2(a);
    float2 fb = __half22float2(b);
    acc.x = fmaf(w, fa.x, acc.x);
    acc.y = fmaf(w, fa.y, acc.y);
    acc.z = fmaf(w, fb.x, acc.z);
    acc.w = fmaf(w, fb.y, acc.w);
}

__global__ __launch_bounds__(256) void agg_kernel(const __half* __restrict__ h16,
                                                  const float* __restrict__ dinv,
                                                  const int* __restrict__ off,
                                                  const int* __restrict__ esrc,
                                                  const float* __restrict__ ew,
                                                  __half* __restrict__ out16, int n) {
    int node = (blockIdx.x * blockDim.x + threadIdx.x) >> 5;
    int lane = threadIdx.x & 31;
    if (node >= n) return;

    const uint2* __restrict__ h2 = (const uint2*)h16;
    float di = dinv[node];
    float wself = di * di;
    float4 acc = make_float4(0.f, 0.f, 0.f, 0.f);
    fma_h4(acc, wself, h2[(size_t)node * 32 + lane]);

    int e = off[node], e1 = off[node + 1];
    for (; e + 3 < e1; e += 4) {
        int s0 = __ldg(&esrc[e]);
        int s1 = __ldg(&esrc[e + 1]);
        int s2 = __ldg(&esrc[e + 2]);
        int s3 = __ldg(&esrc[e + 3]);
        float w0 = __ldg(&ew[e]);
        float w1 = __ldg(&ew[e + 1]);
        float w2 = __ldg(&ew[e + 2]);
        float w3 = __ldg(&ew[e + 3]);
        uint2 v0 = h2[(size_t)s0 * 32 + lane];
        uint2 v1 = h2[(size_t)s1 * 32 + lane];
        uint2 v2 = h2[(size_t)s2 * 32 + lane];
        uint2 v3 = h2[(size_t)s3 * 32 + lane];
        fma_h4(acc, w0, v0);
        fma_h4(acc, w1, v1);
        fma_h4(acc, w2, v2);
        fma_h4(acc, w3, v3);
    }
    for (; e < e1; ++e) {
        int s0 = __ldg(&esrc[e]);
        float w0 = __ldg(&ew[e]);
        fma_h4(acc, w0, h2[(size_t)s0 * 32 + lane]);
    }
    __half2 o0 = __floats2half2_rn(acc.x, acc.y);
    __half2 o1 = __floats2half2_rn(acc.z, acc.w);
    uint2 u;
    u.x = *(uint32_t*)&o0;
    u.y = *(uint32_t*)&o1;
    ((uint2*)out16)[(size_t)node * 32 + lane] = u;
}

// ---------------------------------------------------------------------------
// Plain fp16 HMMA GEMM (single MMA per tile, fp32 accumulate) + bias/ReLU.
// A fp16 [n,128]; W^T fp16 staged in smem (stride 68 u32, conflict-free).
// ---------------------------------------------------------------------------
#define BSTRIDE_U32 68

__device__ __forceinline__ void mma_f16(float* c, const uint32_t* a, uint32_t b0, uint32_t b1) {
    asm volatile(
        "mma.sync.aligned.m16n8k16.row.col.f32.f16.f16.f32 "
        "{%0,%1,%2,%3}, {%4,%5,%6,%7}, {%8,%9}, {%0,%1,%2,%3};"
        : "+f"(c[0]), "+f"(c[1]), "+f"(c[2]), "+f"(c[3])
        : "r"(a[0]), "r"(a[1]), "r"(a[2]), "r"(a[3]), "r"(b0), "r"(b1));
}

template <int RELU, int F16OUT>
__global__ __launch_bounds__(256) void gemm_f16_kernel(
    const __half* __restrict__ A,
    const __half* __restrict__ Wt,
    const float* __restrict__ bias, float* __restrict__ C32,
    __half* __restrict__ C16, int n) {
    extern __shared__ uint32_t sB[];  // 128 * 68 u32 = 34,816 B

    const int tid = threadIdx.x;
    const int warp = tid >> 5;
    const int lane = tid & 31;
    const int quad = lane >> 2;
    const int tq = lane & 3;
    const int row0 = blockIdx.x * 128;

    const uint32_t* W32 = (const uint32_t*)Wt;
#pragma unroll
    for (int i = tid; i < 128 * 64; i += 256) {
        int r = i >> 6, kp = i & 63;
        sB[r * BSTRIDE_U32 + kp] = W32[i];
    }
    __syncthreads();

    const int row_lo = row0 + warp * 16 + quad;
    const int row_hi = row_lo + 8;
    const bool ok_lo = row_lo < n;
    const bool ok_hi = row_hi < n;

    float acc[16][4];
#pragma unroll
    for (int t = 0; t < 16; ++t)
#pragma unroll
        for (int j = 0; j < 4; ++j) acc[t][j] = 0.f;

#pragma unroll
    for (int ks = 0; ks < 8; ++ks) {
        const int k0 = ks * 16;
        uint32_t a[4];
        {
            size_t base_lo = (size_t)row_lo * DD + k0 + 2 * tq;
            size_t base_hi = (size_t)row_hi * DD + k0 + 2 * tq;
            a[0] = ok_lo ? *(const uint32_t*)(A + base_lo) : 0u;
            a[1] = ok_hi ? *(const uint32_t*)(A + base_hi) : 0u;
            a[2] = ok_lo ? *(const uint32_t*)(A + base_lo + 8) : 0u;
            a[3] = ok_hi ? *(const uint32_t*)(A + base_hi + 8) : 0u;
        }
        const int kbase = (k0 >> 1) + tq;
#pragma unroll
        for (int nt = 0; nt < 16; ++nt) {
            int brow = nt * 8 + quad;
            uint32_t b0 = sB[brow * BSTRIDE_U32 + kbase];
            uint32_t b1 = sB[brow * BSTRIDE_U32 + kbase + 4];
            mma_f16(acc[nt], a, b0, b1);
        }
    }

#pragma unroll
    for (int nt = 0; nt < 16; ++nt) {
        int col = nt * 8 + 2 * tq;
        float2 bv = *(const float2*)(bias + col);
        float c0 = acc[nt][0] + bv.x, c1 = acc[nt][1] + bv.y;
        float c2 = acc[nt][2] + bv.x, c3 = acc[nt][3] + bv.y;
        if (RELU) {
            c0 = fmaxf(c0, 0.f); c1 = fmaxf(c1, 0.f);
            c2 = fmaxf(c2, 0.f); c3 = fmaxf(c3, 0.f);
        }
        if (F16OUT) {
            if (ok_lo) *(__half2*)(C16 + (size_t)row_lo * DD + col) = __floats2half2_rn(c0, c1);
            if (ok_hi) *(__half2*)(C16 + (size_t)row_hi * DD + col) = __floats2half2_rn(c2, c3);
        } else {
            if (ok_lo) *(float2*)(C32 + (size_t)row_lo * DD + col) = make_float2(c0, c1);
            if (ok_hi) *(float2*)(C32 + (size_t)row_hi * DD + col) = make_float2(c2, c3);
        }
    }
}

// ---------------------------------------------------------------------------
// Launch: 8 kernels total (prep, scanfill, 3x[agg, gemm])
// ---------------------------------------------------------------------------
extern "C" void kernel_launch(void* const* d_in, const int* in_sizes, int n_in,
                              void* d_out, int out_size) {
    const float* x  = (const float*)d_in[0];
    const int*   ei = (const int*)d_in[1];
    const float* W1 = (const float*)d_in[2];
    const float* b1 = (const float*)d_in[3];
    const float* W2 = (const float*)d_in[4];
    const float* b2 = (const float*)d_in[5];
    const float* W3 = (const float*)d_in[6];
    const float* b3 = (const float*)d_in[7];

    int n = in_sizes[0] / DD;
    int E = in_sizes[1] / 2;
    const int* src = ei;
    const int* dst = ei + E;

    float *dinv, *ew;
    __half *y16, *x16, *act16, *w16;
    int *cnt, *off, *cur, *esrc, *partial, *flag1, *flag2;
    cudaGetSymbolAddress((void**)&y16, g_y16);
    cudaGetSymbolAddress((void**)&x16, g_x16);
    cudaGetSymbolAddress((void**)&act16, g_act16);
    cudaGetSymbolAddress((void**)&w16, g_w16);
    cudaGetSymbolAddress((void**)&dinv, g_dinv);
    cudaGetSymbolAddress((void**)&cnt, g_cnt);
    cudaGetSymbolAddress((void**)&off, g_off);
    cudaGetSymbolAddress((void**)&cur, g_cur);
    cudaGetSymbolAddress((void**)&esrc, g_esrc);
    cudaGetSymbolAddress((void**)&ew, g_ew);
    cudaGetSymbolAddress((void**)&partial, g_partial);
    cudaGetSymbolAddress((void**)&flag1, g_flag1);
    cudaGetSymbolAddress((void**)&flag2, g_flag2);

    float* outp = (float*)d_out;

    const int GEMM_SMEM = 128 * BSTRIDE_U32 * 4;  // 34,816 B
    cudaFuncSetAttribute(gemm_f16_kernel<1, 1>, cudaFuncAttributeMaxDynamicSharedMemorySize,
                         GEMM_SMEM);
    cudaFuncSetAttribute(gemm_f16_kernel<0, 0>, cudaFuncAttributeMaxDynamicSharedMemorySize,
                         GEMM_SMEM);

    int tot4 = n * (DD / 4);
    int ncb = (E + 255) / 256;
    int wsb = (3 * DD * DD + 255) / 256;
    int cvb = (tot4 + 255) / 256;
    int ch = (n + NB_SCAN - 1) / NB_SCAN;

    // --- preprocess: 2 launches ---
    prep_kernel<<<ncb + wsb + cvb, 256>>>(dst, cnt, E, ncb, W1, W2, W3, w16, wsb, x, x16,
                                          tot4, flag1, flag2);
    scanfill_kernel<<<NB_SCAN, 1024>>>(cnt, off, cur, dinv, src, dst, esrc, ew, partial,
                                       flag1, flag2, n, E, ch);

    int gemm_grid = (n + 127) / 128;
    int agg_grid = (n + 7) / 8;

    // Layer 1
    agg_kernel<<<agg_grid, 256>>>(x16, dinv, off, esrc, ew, y16, n);
    gemm_f16_kernel<1, 1><<<gemm_grid, 256, GEMM_SMEM>>>(y16, w16, b1, nullptr, act16, n);
    // Layer 2
    agg_kernel<<<agg_grid, 256>>>(act16, dinv, off, esrc, ew, y16, n);
    gemm_f16_kernel<1, 1><<<gemm_grid, 256, GEMM_SMEM>>>(y16, w16 + DD * DD, b2, nullptr,
                                                         act16, n);
    // Layer 3 (no relu) -> fp32 d_out
    agg_kernel<<<agg_grid, 256>>>(act16, dinv, off, esrc, ew, y16, n);
    gemm_f16_kernel<0, 0><<<gemm_grid, 256, GEMM_SMEM>>>(y16, w16 + 2 * DD * DD, b3, outp,
                                                         nullptr, n);
}

// round 14
// speedup vs baseline: 1.2461x; 1.0108x over previous
#include <cuda_runtime.h>
#include <cuda_bf16.h>
#include <cuda_fp16.h>
#include <cstdint>

#define DD 128
#define MAXN 50016
#define MAXE 800000
#define NB_SCAN 148   // scan/fill blocks (all co-resident => safe grid barrier)

// ---------------- scratch (device globals; allocation-free) ----------------
__device__ __align__(16) __half g_y16[(size_t)MAXN * DD];     // post-agg (fp16)
__device__ __align__(16) __half g_x16[(size_t)MAXN * DD];     // fp16 input copy
__device__ __align__(16) __half g_act16[(size_t)MAXN * DD];   // fp16 activations
__device__ __align__(16) __half g_w16[3 * DD * DD];           // W^T fp16 per layer
__device__ float g_dinv[MAXN];
__device__ __align__(16) int g_cnt[MAXN];   // static-zero; re-zeroed by scanfill each call
__device__ int   g_off[MAXN + 1];
__device__ int   g_cur[MAXN];
__device__ int   g_esrc[MAXE];
__device__ float g_ew[MAXE];
__device__ int   g_partial[256];
__device__ int   g_flag1;
__device__ int   g_flag2;

// ---------------------------------------------------------------------------
// prep: count atomics + W transpose->fp16 + x->fp16 + flag resets. One launch.
// ---------------------------------------------------------------------------
__global__ __launch_bounds__(256) void prep_kernel(
    const int* __restrict__ dst, int* __restrict__ cnt, int E, int ncb,
    const float* __restrict__ W1, const float* __restrict__ W2,
    const float* __restrict__ W3, __half* __restrict__ w16, int wsb,
    const float* __restrict__ x, __half* __restrict__ x16, int tot4,
    int* __restrict__ flag1, int* __restrict__ flag2) {
    int b = (int)blockIdx.x;
    int t = threadIdx.x;
    if (b == 0 && t == 0) {
        *flag1 = 0;
        *flag2 = 0;
    }
    if (b < ncb) {
        int e = b * 256 + t;
        if (e < E) atomicAdd(&cnt[dst[e]], 1);
    } else if (b < ncb + wsb) {
        int i = (b - ncb) * 256 + t;
        if (i < 3 * DD * DD) {
            int layer = i / (DD * DD);
            int j = i - layer * (DD * DD);
            const float* W = (layer == 0) ? W1 : ((layer == 1) ? W2 : W3);
            int nn = j >> 7, kk = j & 127;
            w16[i] = __float2half(W[kk * DD + nn]);
        }
    } else {
        int i = (b - ncb - wsb) * 256 + t;
        if (i < tot4) {
            float4 v = ((const float4*)x)[i];
            __half2 a = __floats2half2_rn(v.x, v.y);
            __half2 c = __floats2half2_rn(v.z, v.w);
            uint2 u;
            u.x = *(uint32_t*)&a;
            u.y = *(uint32_t*)&c;
            ((uint2*)x16)[i] = u;
        }
    }
}

// ---------------------------------------------------------------------------
// scanfill: one kernel, NB_SCAN blocks x 1024 threads (all co-resident).
// ---------------------------------------------------------------------------
__global__ __launch_bounds__(1024) void scanfill_kernel(
    int* __restrict__ cnt, int* __restrict__ off, int* __restrict__ cur,
    float* __restrict__ dinv, const int* __restrict__ src,
    const int* __restrict__ dst, int* __restrict__ esrc, float* __restrict__ ew,
    int* __restrict__ partial, int* __restrict__ flag1, int* __restrict__ flag2,
    int n, int E, int ch) {
    __shared__ int wsum[32];
    __shared__ int sp[NB_SCAN];
    __shared__ int s_base;

    const int b = (int)blockIdx.x;
    const int t = threadIdx.x;
    const int lane = t & 31;
    const int w = t >> 5;
    const int nb = (int)gridDim.x;

    // ---- phase 1: local chunk scan ----
    int i = b * ch + t;
    int c = (t < ch && i < n) ? cnt[i] : 0;
    int incl = c;
#pragma unroll
    for (int o = 1; o < 32; o <<= 1) {
        int u = __shfl_up_sync(0xffffffffu, incl, o);
        if (lane >= o) incl += u;
    }
    if (lane == 31) wsum[w] = incl;
    __syncthreads();
    if (t < 32) {
        int v = wsum[t];
        int orig = v;
#pragma unroll
        for (int o = 1; o < 32; o <<= 1) {
            int u = __shfl_up_sync(0xffffffffu, v, o);
            if (t >= o) v += u;
        }
        int total = __shfl_sync(0xffffffffu, v, 31);
        wsum[t] = v - orig;
        if (t == 0) {
            partial[b] = total;
            __threadfence();
            atomicAdd(flag1, 1);
            while (atomicAdd(flag1, 0) < nb) {}
            __threadfence();
        }
    }
    __syncthreads();

    // ---- phase 2: top scan of nb partials ----
    if (t < nb) sp[t] = partial[t];
    __syncthreads();
    for (int o = 1; o < nb; o <<= 1) {
        int v = (t < nb && t >= o) ? sp[t - o] : 0;
        __syncthreads();
        if (t < nb) sp[t] += v;
        __syncthreads();
    }
    if (t == 0) s_base = (b == 0) ? 0 : sp[b - 1];
    __syncthreads();

    int run = s_base + wsum[w] + (incl - c);
    if (t < ch && i < n) {
        off[i] = run;
        cur[i] = run;
        dinv[i] = rsqrtf((float)(c + 1));
        cnt[i] = 0;
    }
    if (b == 0 && t == 0) off[n] = sp[nb - 1];

    // ---- grid barrier 2 ----
    __threadfence();
    __syncthreads();
    if (t == 0) {
        atomicAdd(flag2, 1);
        while (atomicAdd(flag2, 0) < nb) {}
        __threadfence();
    }
    __syncthreads();

    // ---- phase 3: CSR fill (grid-stride) ----
    for (int e = b * 1024 + t; e < E; e += nb * 1024) {
        int s = src[e];
        int d = dst[e];
        int pos = atomicAdd(&cur[d], 1);
        esrc[pos] = s;
        ew[pos] = dinv[s] * dinv[d];
    }
}

// ---------------------------------------------------------------------------
// Aggregation: fp16 gather, fp32 accumulate, fp16 out.
// ---------------------------------------------------------------------------
__device__ __forceinline__ void fma_h4(float4& acc, float w, uint2 u) {
    __half2 a = *(__half2*)&u.x;
    __half2 b = *(__half2*)&u.y;
    float2 fa = __half22float2(a);
    float2 fb = __half22float2(b);
    acc.x = fmaf(w, fa.x, acc.x);
    acc.y = fmaf(w, fa.y, acc.y);
    acc.z = fmaf(w, fb.x, acc.z);
    acc.w = fmaf(w, fb.y, acc.w);
}

__global__ __launch_bounds__(256) void agg_kernel(const __half* __restrict__ h16,
                                                  const float* __restrict__ dinv,
                                                  const int* __restrict__ off,
                                                  const int* __restrict__ esrc,
                                                  const float* __restrict__ ew,
                                                  __half* __restrict__ out16, int n) {
    int node = (blockIdx.x * blockDim.x + threadIdx.x) >> 5;
    int lane = threadIdx.x & 31;
    if (node >= n) return;

    const uint2* __restrict__ h2 = (const uint2*)h16;
    float di = dinv[node];
    float wself = di * di;
    float4 acc = make_float4(0.f, 0.f, 0.f, 0.f);
    fma_h4(acc, wself, h2[(size_t)node * 32 + lane]);

    int e = off[node], e1 = off[node + 1];
    for (; e + 3 < e1; e += 4) {
        int s0 = __ldg(&esrc[e]);
        int s1 = __ldg(&esrc[e + 1]);
        int s2 = __ldg(&esrc[e + 2]);
        int s3 = __ldg(&esrc[e + 3]);
        float w0 = __ldg(&ew[e]);
        float w1 = __ldg(&ew[e + 1]);
        float w2 = __ldg(&ew[e + 2]);
        float w3 = __ldg(&ew[e + 3]);
        uint2 v0 = h2[(size_t)s0 * 32 + lane];
        uint2 v1 = h2[(size_t)s1 * 32 + lane];
        uint2 v2 = h2[(size_t)s2 * 32 + lane];
        uint2 v3 = h2[(size_t)s3 * 32 + lane];
        fma_h4(acc, w0, v0);
        fma_h4(acc, w1, v1);
        fma_h4(acc, w2, v2);
        fma_h4(acc, w3, v3);
    }
    for (; e < e1; ++e) {
        int s0 = __ldg(&esrc[e]);
        float w0 = __ldg(&ew[e]);
        fma_h4(acc, w0, h2[(size_t)s0 * 32 + lane]);
    }
    __half2 o0 = __floats2half2_rn(acc.x, acc.y);
    __half2 o1 = __floats2half2_rn(acc.z, acc.w);
    uint2 u;
    u.x = *(uint32_t*)&o0;
    u.y = *(uint32_t*)&o1;
    ((uint2*)out16)[(size_t)node * 32 + lane] = u;
}

// ---------------------------------------------------------------------------
// Plain fp16 HMMA GEMM (single MMA per tile, fp32 accumulate) + bias/ReLU.
// A fp16 [n,128]; W^T fp16 staged in smem (stride 68 u32, conflict-free).
// ---------------------------------------------------------------------------
#define BSTRIDE_U32 68

__device__ __forceinline__ void mma_f16(float* c, const uint32_t* a, uint32_t b0, uint32_t b1) {
    asm volatile(
        "mma.sync.aligned.m16n8k16.row.col.f32.f16.f16.f32 "
        "{%0,%1,%2,%3}, {%4,%5,%6,%7}, {%8,%9}, {%0,%1,%2,%3};"
        : "+f"(c[0]), "+f"(c[1]), "+f"(c[2]), "+f"(c[3])
        : "r"(a[0]), "r"(a[1]), "r"(a[2]), "r"(a[3]), "r"(b0), "r"(b1));
}

template <int RELU, int F16OUT>
__global__ __launch_bounds__(256) void gemm_f16_kernel(
    const __half* __restrict__ A,
    const __half* __restrict__ Wt,
    const float* __restrict__ bias, float* __restrict__ C32,
    __half* __restrict__ C16, int n) {
    extern __shared__ uint32_t sB[];  // 128 * 68 u32 = 34,816 B

    const int tid = threadIdx.x;
    const int warp = tid >> 5;
    const int lane = tid & 31;
    const int quad = lane >> 2;
    const int tq = lane & 3;
    const int row0 = blockIdx.x * 128;

    const uint32_t* W32 = (const uint32_t*)Wt;
#pragma unroll
    for (int i = tid; i < 128 * 64; i += 256) {
        int r = i >> 6, kp = i & 63;
        sB[r * BSTRIDE_U32 + kp] = W32[i];
    }
    __syncthreads();

    const int row_lo = row0 + warp * 16 + quad;
    const int row_hi = row_lo + 8;
    const bool ok_lo = row_lo < n;
    const bool ok_hi = row_hi < n;

    float acc[16][4];
#pragma unroll
    for (int t = 0; t < 16; ++t)
#pragma unroll
        for (int j = 0; j < 4; ++j) acc[t][j] = 0.f;

#pragma unroll
    for (int ks = 0; ks < 8; ++ks) {
        const int k0 = ks * 16;
        uint32_t a[4];
        {
            size_t base_lo = (size_t)row_lo * DD + k0 + 2 * tq;
            size_t base_hi = (size_t)row_hi * DD + k0 + 2 * tq;
            a[0] = ok_lo ? *(const uint32_t*)(A + base_lo) : 0u;
            a[1] = ok_hi ? *(const uint32_t*)(A + base_hi) : 0u;
            a[2] = ok_lo ? *(const uint32_t*)(A + base_lo + 8) : 0u;
            a[3] = ok_hi ? *(const uint32_t*)(A + base_hi + 8) : 0u;
        }
        const int kbase = (k0 >> 1) + tq;
#pragma unroll
        for (int nt = 0; nt < 16; ++nt) {
            int brow = nt * 8 + quad;
            uint32_t b0 = sB[brow * BSTRIDE_U32 + kbase];
            uint32_t b1 = sB[brow * BSTRIDE_U32 + kbase + 4];
            mma_f16(acc[nt], a, b0, b1);
        }
    }

#pragma unroll
    for (int nt = 0; nt < 16; ++nt) {
        int col = nt * 8 + 2 * tq;
        float2 bv = *(const float2*)(bias + col);
        float c0 = acc[nt][0] + bv.x, c1 = acc[nt][1] + bv.y;
        float c2 = acc[nt][2] + bv.x, c3 = acc[nt][3] + bv.y;
        if (RELU) {
            c0 = fmaxf(c0, 0.f); c1 = fmaxf(c1, 0.f);
            c2 = fmaxf(c2, 0.f); c3 = fmaxf(c3, 0.f);
        }
        if (F16OUT) {
            if (ok_lo) *(__half2*)(C16 + (size_t)row_lo * DD + col) = __floats2half2_rn(c0, c1);
            if (ok_hi) *(__half2*)(C16 + (size_t)row_hi * DD + col) = __floats2half2_rn(c2, c3);
        } else {
            if (ok_lo) *(float2*)(C32 + (size_t)row_lo * DD + col) = make_float2(c0, c1);
            if (ok_hi) *(float2*)(C32 + (size_t)row_hi * DD + col) = make_float2(c2, c3);
        }
    }
}

// ---------------------------------------------------------------------------
// Launch: 8 kernels total (prep, scanfill, 3x[agg, gemm])
// ---------------------------------------------------------------------------
extern "C" void kernel_launch(void* const* d_in, const int* in_sizes, int n_in,
                              void* d_out, int out_size) {
    const float* x  = (const float*)d_in[0];
    const int*   ei = (const int*)d_in[1];
    const float* W1 = (const float*)d_in[2];
    const float* b1 = (const float*)d_in[3];
    const float* W2 = (const float*)d_in[4];
    const float* b2 = (const float*)d_in[5];
    const float* W3 = (const float*)d_in[6];
    const float* b3 = (const float*)d_in[7];

    int n = in_sizes[0] / DD;
    int E = in_sizes[1] / 2;
    const int* src = ei;
    const int* dst = ei + E;

    float *dinv, *ew;
    __half *y16, *x16, *act16, *w16;
    int *cnt, *off, *cur, *esrc, *partial, *flag1, *flag2;
    cudaGetSymbolAddress((void**)&y16, g_y16);
    cudaGetSymbolAddress((void**)&x16, g_x16);
    cudaGetSymbolAddress((void**)&act16, g_act16);
    cudaGetSymbolAddress((void**)&w16, g_w16);
    cudaGetSymbolAddress((void**)&dinv, g_dinv);
    cudaGetSymbolAddress((void**)&cnt, g_cnt);
    cudaGetSymbolAddress((void**)&off, g_off);
    cudaGetSymbolAddress((void**)&cur, g_cur);
    cudaGetSymbolAddress((void**)&esrc, g_esrc);
    cudaGetSymbolAddress((void**)&ew, g_ew);
    cudaGetSymbolAddress((void**)&partial, g_partial);
    cudaGetSymbolAddress((void**)&flag1, g_flag1);
    cudaGetSymbolAddress((void**)&flag2, g_flag2);

    float* outp = (float*)d_out;

    const int GEMM_SMEM = 128 * BSTRIDE_U32 * 4;  // 34,816 B
    cudaFuncSetAttribute(gemm_f16_kernel<1, 1>, cudaFuncAttributeMaxDynamicSharedMemorySize,
                         GEMM_SMEM);
    cudaFuncSetAttribute(gemm_f16_kernel<0, 0>, cudaFuncAttributeMaxDynamicSharedMemorySize,
                         GEMM_SMEM);

    int tot4 = n * (DD / 4);
    int ncb = (E + 255) / 256;
    int wsb = (3 * DD * DD + 255) / 256;
    int cvb = (tot4 + 255) / 256;
    int ch = (n + NB_SCAN - 1) / NB_SCAN;

    // --- preprocess: 2 launches ---
    prep_kernel<<<ncb + wsb + cvb, 256>>>(dst, cnt, E, ncb, W1, W2, W3, w16, wsb, x, x16,
                                          tot4, flag1, flag2);
    scanfill_kernel<<<NB_SCAN, 1024>>>(cnt, off, cur, dinv, src, dst, esrc, ew, partial,
                                       flag1, flag2, n, E, ch);

    int gemm_grid = (n + 127) / 128;
    int agg_grid = (n + 7) / 8;

    // Layer 1
    agg_kernel<<<agg_grid, 256>>>(x16, dinv, off, esrc, ew, y16, n);
    gemm_f16_kernel<1, 1><<<gemm_grid, 256, GEMM_SMEM>>>(y16, w16, b1, nullptr, act16, n);
    // Layer 2
    agg_kernel<<<agg_grid, 256>>>(act16, dinv, off, esrc, ew, y16, n);
    gemm_f16_kernel<1, 1><<<gemm_grid, 256, GEMM_SMEM>>>(y16, w16 + DD * DD, b2, nullptr,
                                                         act16, n);
    // Layer 3 (no relu) -> fp32 d_out
    agg_kernel<<<agg_grid, 256>>>(act16, dinv, off, esrc, ew, y16, n);
    gemm_f16_kernel<0, 0><<<gemm_grid, 256, GEMM_SMEM>>>(y16, w16 + 2 * DD * DD, b3, outp,
                                                         nullptr, n);
}